// round 1
// baseline (speedup 1.0000x reference)
#include <cuda_runtime.h>
#include <math.h>

#define NNODES 80000
#define DIM    128
#define DEMB   64
#define NT     128
#define NG     8000
#define NUMP   40000

// ---------------- scratch (static device arrays; no allocation) ----------------
__device__ __align__(16) float g_deg[NNODES];
__device__             int    g_flag[NNODES];
__device__ __align__(16) float g_xa[(size_t)NNODES * DIM];   // agg1 accumulator
__device__ __align__(16) float g_h [(size_t)NNODES * DIM];   // relu(agg1@W1+b1)
__device__ __align__(16) float g_p [(size_t)NNODES * DEMB];  // h@W2
__device__ __align__(16) float g_pa[(size_t)NNODES * DEMB];  // agg2 accumulator (filtered)
__device__ __align__(16) float g_At[DIM * NT];               // A transposed [k][t]
__device__ __align__(16) float g_Bt[(size_t)DIM * NG];       // B transposed [k][g]

// ---------------- zero scratch ----------------
__global__ void zero_kernel() {
    int i = blockIdx.x * blockDim.x + threadIdx.x;
    float4 z = make_float4(0.f, 0.f, 0.f, 0.f);
    if (i < NNODES * DIM / 4)  reinterpret_cast<float4*>(g_xa)[i] = z;
    if (i < NNODES * DEMB / 4) reinterpret_cast<float4*>(g_pa)[i] = z;
    if (i < NNODES) { g_deg[i] = 0.f; g_flag[i] = 0; }
}

__global__ void flag_kernel(const int* __restrict__ tf, const int* __restrict__ gene) {
    int i = blockIdx.x * blockDim.x + threadIdx.x;
    if (i < NT) g_flag[NUMP + tf[i]]   = 1;
    if (i < NG) g_flag[NUMP + gene[i]] = 1;
}

// ---------------- aggregation 1: xa[dst] += x[src]; deg[dst] += 1 ----------------
// one warp per edge; lane handles 4 floats via vector red
__global__ void agg1_kernel(const float* __restrict__ x, const int* __restrict__ src,
                            const int* __restrict__ dst, int ne) {
    int e = blockIdx.x * (blockDim.x >> 5) + (threadIdx.x >> 5);
    if (e >= ne) return;
    int lane = threadIdx.x & 31;
    int s = src[e], d = dst[e];
    float4 v = reinterpret_cast<const float4*>(x + (size_t)s * DIM)[lane];
    float* o = g_xa + (size_t)d * DIM + (size_t)lane * 4;
    asm volatile("red.global.add.v4.f32 [%0], {%1,%2,%3,%4};"
                 :: "l"(o), "f"(v.x), "f"(v.y), "f"(v.z), "f"(v.w) : "memory");
    if (lane == 0) atomicAdd(g_deg + d, 1.0f);
}

// ---------------- aggregation 2 (D=64, dst-filtered): pa[dst] += p[src] ----------------
// 16 threads per edge
__global__ void agg2_kernel(const int* __restrict__ src, const int* __restrict__ dst, int ne) {
    int e = blockIdx.x * (blockDim.x >> 4) + (threadIdx.x >> 4);
    if (e >= ne) return;
    int lane = threadIdx.x & 15;
    int d = dst[e];
    if (!g_flag[d]) return;
    int s = src[e];
    float4 v = reinterpret_cast<const float4*>(g_p + (size_t)s * DEMB)[lane];
    float* o = g_pa + (size_t)d * DEMB + (size_t)lane * 4;
    asm volatile("red.global.add.v4.f32 [%0], {%1,%2,%3,%4};"
                 :: "l"(o), "f"(v.x), "f"(v.y), "f"(v.z), "f"(v.w) : "memory");
}

// ---------------- dense GEMM: Out = act( scale(In) @ W + bias ) ----------------
// In: rows x 128, W: 128 x N (N=128 or 64). 256 threads, 32-row tile per block.
// Thread (tr,tc) computes 4 rows x (N/32) cols.
template<int N, bool RELU, bool SCALE>
__global__ __launch_bounds__(256) void gemm_kernel(
    const float* __restrict__ In, const float* __restrict__ W,
    const float* __restrict__ bias, float* __restrict__ Out, int rows) {
    extern __shared__ float sm[];
    float* Ws = sm;              // 128*N
    float* Is = sm + 128 * N;    // 32*128, row-major [r][d]
    int tid = threadIdx.x;

    for (int i = tid; i < 128 * N / 4; i += 256)
        reinterpret_cast<float4*>(Ws)[i] = reinterpret_cast<const float4*>(W)[i];

    int row0 = blockIdx.x * 32;
    for (int i = tid; i < 32 * DIM / 4; i += 256) {
        int r = i >> 5, c4 = i & 31;
        int row = row0 + r;
        float4 v = make_float4(0.f, 0.f, 0.f, 0.f);
        if (row < rows) {
            v = reinterpret_cast<const float4*>(In + (size_t)row * DIM)[c4];
            if (SCALE) {
                float sc = 1.f / fmaxf(g_deg[row], 1.f);
                v.x *= sc; v.y *= sc; v.z *= sc; v.w *= sc;
            }
        }
        reinterpret_cast<float4*>(Is)[i] = v;
    }
    __syncthreads();

    constexpr int CV = N / 32;
    int tr = tid >> 5, tc = tid & 31;
    float acc[4][CV];
#pragma unroll
    for (int i = 0; i < 4; i++)
#pragma unroll
        for (int j = 0; j < CV; j++) acc[i][j] = 0.f;

#pragma unroll 8
    for (int d = 0; d < DIM; d++) {
        float w[CV];
        if constexpr (CV == 4) {
            float4 wv = reinterpret_cast<const float4*>(Ws + (size_t)d * N)[tc];
            w[0] = wv.x; w[1] = wv.y; w[2] = wv.z; w[3] = wv.w;
        } else {
            float2 wv = reinterpret_cast<const float2*>(Ws + (size_t)d * N)[tc];
            w[0] = wv.x; w[1] = wv.y;
        }
        float a0 = Is[(tr * 4 + 0) * DIM + d];
        float a1 = Is[(tr * 4 + 1) * DIM + d];
        float a2 = Is[(tr * 4 + 2) * DIM + d];
        float a3 = Is[(tr * 4 + 3) * DIM + d];
#pragma unroll
        for (int j = 0; j < CV; j++) {
            acc[0][j] = fmaf(a0, w[j], acc[0][j]);
            acc[1][j] = fmaf(a1, w[j], acc[1][j]);
            acc[2][j] = fmaf(a2, w[j], acc[2][j]);
            acc[3][j] = fmaf(a3, w[j], acc[3][j]);
        }
    }

#pragma unroll
    for (int i = 0; i < 4; i++) {
        int row = row0 + tr * 4 + i;
        if (row >= rows) continue;
#pragma unroll
        for (int j = 0; j < CV; j++) {
            int c = tc * CV + j;
            float v = acc[i][j] + (bias ? bias[c] : 0.f);
            if (RELU) v = fmaxf(v, 0.f);
            Out[(size_t)row * N + c] = v;
        }
    }
}

// ---------------- half-MLP: OutT[k][r] = sum_d (pa[node_r][d]/deg + b2[d]) * Whalf[d][k] (+bm1[k]) ----------------
__global__ __launch_bounds__(128) void half_mlp_kernel(
    const int* __restrict__ list, int nrows,
    const float* __restrict__ Whalf, const float* __restrict__ b2,
    const float* __restrict__ bm1, float* __restrict__ OutT, int ldo) {
    __shared__ float Ws[DEMB * DIM];
    __shared__ float es[DEMB];
    int tid = threadIdx.x;  // 128

    for (int i = tid; i < DEMB * DIM / 4; i += 128)
        reinterpret_cast<float4*>(Ws)[i] = reinterpret_cast<const float4*>(Whalf)[i];
    float base = bm1 ? bm1[tid] : 0.f;

    for (int r = blockIdx.x; r < nrows; r += gridDim.x) {
        __syncthreads();
        if (tid < DEMB) {
            int node = NUMP + list[r];
            float sc = 1.f / fmaxf(g_deg[node], 1.f);
            es[tid] = g_pa[(size_t)node * DEMB + tid] * sc + b2[tid];
        }
        __syncthreads();
        float acc = base;
#pragma unroll 8
        for (int d = 0; d < DEMB; d++) acc = fmaf(es[d], Ws[d * DIM + tid], acc);
        OutT[(size_t)tid * ldo + r] = acc;
    }
}

// ---------------- pair kernel: out[t*NG+g] = softmax( relu(A[t]+B[g]) @ Wm2 + bm2 ) ----------------
// block: 32 genes x all 128 tfs. warp w handles t = w + 8*i, lane = local gene.
__global__ __launch_bounds__(256) void pair_kernel(
    const float* __restrict__ Wm2, const float* __restrict__ bm2, float* __restrict__ out) {
    extern __shared__ float sm[];
    float* As = sm;                       // [k][t] 128*128
    float* Bs = sm + DIM * NT;            // [k][gl] 128*32
    float2* w2 = reinterpret_cast<float2*>(sm + DIM * NT + DIM * 32);
    int tid = threadIdx.x;  // 256

    for (int i = tid; i < DIM * NT / 4; i += 256)
        reinterpret_cast<float4*>(As)[i] = reinterpret_cast<const float4*>(g_At)[i];
    int g0 = blockIdx.x * 32;
    for (int i = tid; i < DIM * 32; i += 256) {
        int k = i >> 5, gl = i & 31;
        Bs[i] = g_Bt[(size_t)k * NG + g0 + gl];
    }
    if (tid < DIM) w2[tid] = reinterpret_cast<const float2*>(Wm2)[tid];
    __syncthreads();

    float bo0 = bm2[0], bo1 = bm2[1];
    int lane = tid & 31, warp = tid >> 5;
    float acc0[16], acc1[16];
#pragma unroll
    for (int i = 0; i < 16; i++) { acc0[i] = 0.f; acc1[i] = 0.f; }

#pragma unroll 4
    for (int k = 0; k < DIM; k++) {
        float bv = Bs[k * 32 + lane];
        float2 w = w2[k];
#pragma unroll
        for (int i = 0; i < 16; i++) {
            float a = As[k * DIM + warp + 8 * i];
            float v = fmaxf(a + bv, 0.f);
            acc0[i] = fmaf(v, w.x, acc0[i]);
            acc1[i] = fmaf(v, w.y, acc1[i]);
        }
    }

#pragma unroll
    for (int i = 0; i < 16; i++) {
        int t = warp + 8 * i;
        float o0 = acc0[i] + bo0, o1 = acc1[i] + bo1;
        float m  = fmaxf(o0, o1);
        float e0 = __expf(o0 - m), e1 = __expf(o1 - m);
        float inv = 1.f / (e0 + e1);
        reinterpret_cast<float2*>(out)[(size_t)t * NG + g0 + lane] = make_float2(e0 * inv, e1 * inv);
    }
}

// ---------------- launch ----------------
extern "C" void kernel_launch(void* const* d_in, const int* in_sizes, int n_in,
                              void* d_out, int out_size) {
    const float* x   = (const float*)d_in[0];
    const float* W1  = (const float*)d_in[1];
    const float* b1  = (const float*)d_in[2];
    const float* W2  = (const float*)d_in[3];
    const float* b2  = (const float*)d_in[4];
    const float* Wm1 = (const float*)d_in[5];
    const float* bm1 = (const float*)d_in[6];
    const float* Wm2 = (const float*)d_in[7];
    const float* bm2 = (const float*)d_in[8];
    const int* edges = (const int*)d_in[9];
    const int* tf    = (const int*)d_in[11];
    const int* gene  = (const int*)d_in[12];
    int ne = in_sizes[9] / 2;
    const int* src = edges;
    const int* dst = edges + ne;
    float* out = (float*)d_out;

    // opt-in shared memory (>48KB), idempotent every call
    cudaFuncSetAttribute(gemm_kernel<128, true,  true >, cudaFuncAttributeMaxDynamicSharedMemorySize, (128*128 + 32*128) * 4);
    cudaFuncSetAttribute(gemm_kernel<64,  false, false>, cudaFuncAttributeMaxDynamicSharedMemorySize, (128*64  + 32*128) * 4);
    cudaFuncSetAttribute(pair_kernel, cudaFuncAttributeMaxDynamicSharedMemorySize, (DIM*NT + DIM*32) * 4 + DIM * 8);

    void *p_xa, *p_h, *p_p, *p_At, *p_Bt;
    cudaGetSymbolAddress(&p_xa, g_xa);
    cudaGetSymbolAddress(&p_h,  g_h);
    cudaGetSymbolAddress(&p_p,  g_p);
    cudaGetSymbolAddress(&p_At, g_At);
    cudaGetSymbolAddress(&p_Bt, g_Bt);

    zero_kernel<<<(NNODES * DIM / 4 + 255) / 256, 256>>>();
    agg1_kernel<<<(ne + 7) / 8, 256>>>(x, src, dst, ne);
    gemm_kernel<128, true, true><<<(NNODES + 31) / 32, 256, (128*128 + 32*128) * 4>>>(
        (const float*)p_xa, W1, b1, (float*)p_h, NNODES);
    gemm_kernel<64, false, false><<<(NNODES + 31) / 32, 256, (128*64 + 32*128) * 4>>>(
        (const float*)p_h, W2, nullptr, (float*)p_p, NNODES);
    flag_kernel<<<(NG + 255) / 256, 256>>>(tf, gene);
    agg2_kernel<<<(ne + 15) / 16, 256>>>(src, dst, ne);
    half_mlp_kernel<<<NT, 128>>>(tf, NT, Wm1, b2, nullptr, (float*)p_At, NT);
    half_mlp_kernel<<<1000, 128>>>(gene, NG, Wm1 + 64 * DIM, b2, bm1, (float*)p_Bt, NG);
    pair_kernel<<<NG / 32, 256, (DIM*NT + DIM*32) * 4 + DIM * 8>>>(Wm2, bm2, out);
}

// round 2
// speedup vs baseline: 1.8622x; 1.8622x over previous
#include <cuda_runtime.h>
#include <math.h>

#define NNODES 80000
#define DIM    128
#define DEMB   64
#define NT     128
#define NG     8000
#define NUMP   40000
#define NEMAX  2560000

// ---------------- scratch (static device arrays; no allocation) ----------------
__device__ int g_rowptr[NNODES + 1];
__device__ int g_cursor[NNODES];
__device__ int g_flag[NNODES];
__device__ int g_bsum[128];
__device__ int g_esrc[NEMAX];                                // CSR: src per edge, grouped by dst
__device__ __align__(16) float g_xa[(size_t)NNODES * DIM];   // agg1 output (pre-scaled by 1/deg)
__device__ __align__(16) float g_p [(size_t)NNODES * DEMB];  // relu(xa@W1+b1)@W2
__device__ __align__(16) float g_pa[(size_t)NNODES * DEMB];  // agg2 output (pre-scaled), flagged rows only
__device__ __align__(16) float g_At[DIM * NT];               // A transposed [k][t]
__device__ __align__(16) float g_Bt[(size_t)DIM * NG];       // B transposed [k][g]

// ---------------- zero counters/flags ----------------
__global__ void zero_kernel() {
    int i = blockIdx.x * blockDim.x + threadIdx.x;
    if (i <= NNODES) g_rowptr[i] = 0;
    if (i <  NNODES) { g_cursor[i] = 0; g_flag[i] = 0; }
}

__global__ void flag_kernel(const int* __restrict__ tf, const int* __restrict__ gene) {
    int i = blockIdx.x * blockDim.x + threadIdx.x;
    if (i < NT) g_flag[NUMP + tf[i]]   = 1;
    if (i < NG) g_flag[NUMP + gene[i]] = 1;
}

// ---------------- CSR build: histogram -> scan -> scatter ----------------
__global__ void hist_kernel(const int* __restrict__ dst, int ne) {
    int e = blockIdx.x * blockDim.x + threadIdx.x;
    if (e < ne) atomicAdd(&g_rowptr[dst[e] + 1], 1);
}

// block-level inclusive scan over g_rowptr (1024 elems per block)
__global__ __launch_bounds__(1024) void scan1_kernel() {
    __shared__ int wsum[32];
    int gid = blockIdx.x * 1024 + threadIdx.x;
    int lane = threadIdx.x & 31, wid = threadIdx.x >> 5;
    int s = (gid <= NNODES) ? g_rowptr[gid] : 0;
#pragma unroll
    for (int o = 1; o < 32; o <<= 1) { int t = __shfl_up_sync(0xffffffffu, s, o); if (lane >= o) s += t; }
    if (lane == 31) wsum[wid] = s;
    __syncthreads();
    if (wid == 0) {
        int w = wsum[lane];
#pragma unroll
        for (int o = 1; o < 32; o <<= 1) { int t = __shfl_up_sync(0xffffffffu, w, o); if (lane >= o) w += t; }
        wsum[lane] = w;
    }
    __syncthreads();
    if (wid > 0) s += wsum[wid - 1];
    if (gid <= NNODES) g_rowptr[gid] = s;
    if (threadIdx.x == 1023) g_bsum[blockIdx.x] = s;
}

// scan the block sums (single warp, serial chunks with carry)
__global__ void scan2_kernel(int nb) {
    int lane = threadIdx.x;
    int carry = 0;
    for (int base = 0; base < nb; base += 32) {
        int v = (base + lane < nb) ? g_bsum[base + lane] : 0;
#pragma unroll
        for (int o = 1; o < 32; o <<= 1) { int t = __shfl_up_sync(0xffffffffu, v, o); if (lane >= o) v += t; }
        v += carry;
        if (base + lane < nb) g_bsum[base + lane] = v;
        carry = __shfl_sync(0xffffffffu, v, 31);
    }
}

__global__ __launch_bounds__(1024) void scan3_kernel() {
    int gid = blockIdx.x * 1024 + threadIdx.x;
    if (blockIdx.x > 0 && gid <= NNODES) g_rowptr[gid] += g_bsum[blockIdx.x - 1];
}

__global__ void scatter_kernel(const int* __restrict__ src, const int* __restrict__ dst, int ne) {
    int e = blockIdx.x * blockDim.x + threadIdx.x;
    if (e >= ne) return;
    int d = dst[e];
    int pos = atomicAdd(&g_cursor[d], 1);
    g_esrc[g_rowptr[d] + pos] = src[e];
}

// ---------------- agg1 via CSR: xa[d] = mean_{s in N(d)} x[s]  (warp per dst) ----------------
__global__ __launch_bounds__(256) void agg1_csr_kernel(const float* __restrict__ x) {
    int d = blockIdx.x * 8 + (threadIdx.x >> 5);
    if (d >= NNODES) return;
    int lane = threadIdx.x & 31;
    int beg = g_rowptr[d], end = g_rowptr[d + 1];
    float4 acc = make_float4(0.f, 0.f, 0.f, 0.f);
    int j = beg;
    for (; j + 1 < end; j += 2) {
        int s0 = g_esrc[j], s1 = g_esrc[j + 1];
        float4 v0 = reinterpret_cast<const float4*>(x + (size_t)s0 * DIM)[lane];
        float4 v1 = reinterpret_cast<const float4*>(x + (size_t)s1 * DIM)[lane];
        acc.x += v0.x + v1.x; acc.y += v0.y + v1.y;
        acc.z += v0.z + v1.z; acc.w += v0.w + v1.w;
    }
    if (j < end) {
        int s0 = g_esrc[j];
        float4 v0 = reinterpret_cast<const float4*>(x + (size_t)s0 * DIM)[lane];
        acc.x += v0.x; acc.y += v0.y; acc.z += v0.z; acc.w += v0.w;
    }
    float inv = 1.f / fmaxf((float)(end - beg), 1.f);
    acc.x *= inv; acc.y *= inv; acc.z *= inv; acc.w *= inv;
    reinterpret_cast<float4*>(g_xa + (size_t)d * DIM)[lane] = acc;
}

// ---------------- agg2 via CSR (flagged dsts only): pa[d] = mean p[s] ----------------
__global__ __launch_bounds__(256) void agg2_csr_kernel() {
    int d = blockIdx.x * 8 + (threadIdx.x >> 5);
    if (d >= NNODES) return;
    if (!g_flag[d]) return;
    int lane = threadIdx.x & 31;
    int beg = g_rowptr[d], end = g_rowptr[d + 1];
    float2 acc = make_float2(0.f, 0.f);
    int j = beg;
    for (; j + 1 < end; j += 2) {
        int s0 = g_esrc[j], s1 = g_esrc[j + 1];
        float2 v0 = reinterpret_cast<const float2*>(g_p + (size_t)s0 * DEMB)[lane];
        float2 v1 = reinterpret_cast<const float2*>(g_p + (size_t)s1 * DEMB)[lane];
        acc.x += v0.x + v1.x; acc.y += v0.y + v1.y;
    }
    if (j < end) {
        int s0 = g_esrc[j];
        float2 v0 = reinterpret_cast<const float2*>(g_p + (size_t)s0 * DEMB)[lane];
        acc.x += v0.x; acc.y += v0.y;
    }
    float inv = 1.f / fmaxf((float)(end - beg), 1.f);
    reinterpret_cast<float2*>(g_pa + (size_t)d * DEMB)[lane] = make_float2(acc.x * inv, acc.y * inv);
}

// ---------------- fused GEMM: p = relu(xa@W1 + b1) @ W2   (64 rows/block, 512 threads) ----------------
__global__ __launch_bounds__(512) void fused_gemm_kernel(
    const float* __restrict__ W1, const float* __restrict__ b1,
    const float* __restrict__ W2) {
    extern __shared__ float sm[];
    float* W1s = sm;                       // 128*128
    float* W2s = W1s + 128 * 128;          // 128*64
    float* Is  = W2s + 128 * 64;           // 64*128
    float* Hs  = Is  + 64 * 128;           // 64*128
    float* b1s = Hs  + 64 * 128;           // 128
    int tid = threadIdx.x;

    for (int i = tid; i < 128 * 128 / 4; i += 512)
        reinterpret_cast<float4*>(W1s)[i] = reinterpret_cast<const float4*>(W1)[i];
    for (int i = tid; i < 128 * 64 / 4; i += 512)
        reinterpret_cast<float4*>(W2s)[i] = reinterpret_cast<const float4*>(W2)[i];
    if (tid < 128) b1s[tid] = b1[tid];

    int row0 = blockIdx.x * 64;  // 1250 blocks * 64 = 80000 exact
    for (int i = tid; i < 64 * DIM / 4; i += 512)
        reinterpret_cast<float4*>(Is)[i] =
            reinterpret_cast<const float4*>(g_xa + (size_t)row0 * DIM)[i];
    __syncthreads();

    int tr = tid >> 5, tc = tid & 31;   // tr 0..15, tc 0..31

    // phase 1: H = relu(Is @ W1 + b1); thread -> 4 rows x 4 cols
    {
        float acc[4][4];
#pragma unroll
        for (int i = 0; i < 4; i++)
#pragma unroll
            for (int j = 0; j < 4; j++) acc[i][j] = 0.f;

        for (int d0 = 0; d0 < DIM; d0 += 4) {
            float ar[4][4];
#pragma unroll
            for (int i = 0; i < 4; i++) {
                float4 t = reinterpret_cast<const float4*>(Is + (tr * 4 + i) * DIM)[d0 >> 2];
                ar[i][0] = t.x; ar[i][1] = t.y; ar[i][2] = t.z; ar[i][3] = t.w;
            }
#pragma unroll
            for (int dd = 0; dd < 4; dd++) {
                float4 w = reinterpret_cast<const float4*>(W1s + (d0 + dd) * 128)[tc];
#pragma unroll
                for (int i = 0; i < 4; i++) {
                    acc[i][0] = fmaf(ar[i][dd], w.x, acc[i][0]);
                    acc[i][1] = fmaf(ar[i][dd], w.y, acc[i][1]);
                    acc[i][2] = fmaf(ar[i][dd], w.z, acc[i][2]);
                    acc[i][3] = fmaf(ar[i][dd], w.w, acc[i][3]);
                }
            }
        }
#pragma unroll
        for (int i = 0; i < 4; i++) {
            float4 o;
            o.x = fmaxf(acc[i][0] + b1s[tc * 4 + 0], 0.f);
            o.y = fmaxf(acc[i][1] + b1s[tc * 4 + 1], 0.f);
            o.z = fmaxf(acc[i][2] + b1s[tc * 4 + 2], 0.f);
            o.w = fmaxf(acc[i][3] + b1s[tc * 4 + 3], 0.f);
            reinterpret_cast<float4*>(Hs + (tr * 4 + i) * DIM)[tc] = o;
        }
    }
    __syncthreads();

    // phase 2: P = Hs @ W2; thread -> 4 rows x 2 cols
    {
        float acc[4][2];
#pragma unroll
        for (int i = 0; i < 4; i++) { acc[i][0] = 0.f; acc[i][1] = 0.f; }

        for (int d0 = 0; d0 < DIM; d0 += 4) {
            float ar[4][4];
#pragma unroll
            for (int i = 0; i < 4; i++) {
                float4 t = reinterpret_cast<const float4*>(Hs + (tr * 4 + i) * DIM)[d0 >> 2];
                ar[i][0] = t.x; ar[i][1] = t.y; ar[i][2] = t.z; ar[i][3] = t.w;
            }
#pragma unroll
            for (int dd = 0; dd < 4; dd++) {
                float2 w = reinterpret_cast<const float2*>(W2s + (d0 + dd) * 64)[tc];
#pragma unroll
                for (int i = 0; i < 4; i++) {
                    acc[i][0] = fmaf(ar[i][dd], w.x, acc[i][0]);
                    acc[i][1] = fmaf(ar[i][dd], w.y, acc[i][1]);
                }
            }
        }
#pragma unroll
        for (int i = 0; i < 4; i++) {
            int row = row0 + tr * 4 + i;
            reinterpret_cast<float2*>(g_p + (size_t)row * DEMB)[tc] =
                make_float2(acc[i][0], acc[i][1]);
        }
    }
}

// ---------------- half-MLP: OutT[k][r] = sum_d (pa[node_r][d] + b2[d]) * Whalf[d][k] (+bm1[k]) ----------------
__global__ __launch_bounds__(128) void half_mlp_kernel(
    const int* __restrict__ list, int nrows,
    const float* __restrict__ Whalf, const float* __restrict__ b2,
    const float* __restrict__ bm1, float* __restrict__ OutT, int ldo) {
    __shared__ float Ws[DEMB * DIM];
    __shared__ float es[DEMB];
    int tid = threadIdx.x;  // 128

    for (int i = tid; i < DEMB * DIM / 4; i += 128)
        reinterpret_cast<float4*>(Ws)[i] = reinterpret_cast<const float4*>(Whalf)[i];
    float base = bm1 ? bm1[tid] : 0.f;

    for (int r = blockIdx.x; r < nrows; r += gridDim.x) {
        __syncthreads();
        if (tid < DEMB) {
            int node = NUMP + list[r];
            es[tid] = g_pa[(size_t)node * DEMB + tid] + b2[tid];
        }
        __syncthreads();
        float acc = base;
#pragma unroll 8
        for (int d = 0; d < DEMB; d++) acc = fmaf(es[d], Ws[d * DIM + tid], acc);
        OutT[(size_t)tid * ldo + r] = acc;
    }
}

// ---------------- pair kernel: out[t*NG+g] = softmax( relu(A[t]+B[g]) @ Wm2 + bm2 ) ----------------
__global__ __launch_bounds__(256) void pair_kernel(
    const float* __restrict__ Wm2, const float* __restrict__ bm2, float* __restrict__ out) {
    extern __shared__ float sm[];
    float* As = sm;                       // [k][t] 128*128
    float* Bs = sm + DIM * NT;            // [k][gl] 128*32
    float2* w2 = reinterpret_cast<float2*>(sm + DIM * NT + DIM * 32);
    int tid = threadIdx.x;  // 256

    for (int i = tid; i < DIM * NT / 4; i += 256)
        reinterpret_cast<float4*>(As)[i] = reinterpret_cast<const float4*>(g_At)[i];
    int g0 = blockIdx.x * 32;
    for (int i = tid; i < DIM * 32; i += 256) {
        int k = i >> 5, gl = i & 31;
        Bs[i] = g_Bt[(size_t)k * NG + g0 + gl];
    }
    if (tid < DIM) w2[tid] = reinterpret_cast<const float2*>(Wm2)[tid];
    __syncthreads();

    float bo0 = bm2[0], bo1 = bm2[1];
    int lane = tid & 31, warp = tid >> 5;
    float acc0[16], acc1[16];
#pragma unroll
    for (int i = 0; i < 16; i++) { acc0[i] = 0.f; acc1[i] = 0.f; }

#pragma unroll 4
    for (int k = 0; k < DIM; k++) {
        float bv = Bs[k * 32 + lane];
        float2 w = w2[k];
#pragma unroll
        for (int i = 0; i < 16; i++) {
            float a = As[k * DIM + warp + 8 * i];
            float v = fmaxf(a + bv, 0.f);
            acc0[i] = fmaf(v, w.x, acc0[i]);
            acc1[i] = fmaf(v, w.y, acc1[i]);
        }
    }

#pragma unroll
    for (int i = 0; i < 16; i++) {
        int t = warp + 8 * i;
        float o0 = acc0[i] + bo0, o1 = acc1[i] + bo1;
        float m  = fmaxf(o0, o1);
        float e0 = __expf(o0 - m), e1 = __expf(o1 - m);
        float inv = 1.f / (e0 + e1);
        reinterpret_cast<float2*>(out)[(size_t)t * NG + g0 + lane] = make_float2(e0 * inv, e1 * inv);
    }
}

// ---------------- launch ----------------
extern "C" void kernel_launch(void* const* d_in, const int* in_sizes, int n_in,
                              void* d_out, int out_size) {
    const float* x   = (const float*)d_in[0];
    const float* W1  = (const float*)d_in[1];
    const float* b1  = (const float*)d_in[2];
    const float* W2  = (const float*)d_in[3];
    const float* b2  = (const float*)d_in[4];
    const float* Wm1 = (const float*)d_in[5];
    const float* bm1 = (const float*)d_in[6];
    const float* Wm2 = (const float*)d_in[7];
    const float* bm2 = (const float*)d_in[8];
    const int* edges = (const int*)d_in[9];
    const int* tf    = (const int*)d_in[11];
    const int* gene  = (const int*)d_in[12];
    int ne = in_sizes[9] / 2;
    const int* src = edges;
    const int* dst = edges + ne;
    float* out = (float*)d_out;

    const int fused_smem = (128 * 128 + 128 * 64 + 64 * 128 + 64 * 128 + 128) * 4;
    cudaFuncSetAttribute(fused_gemm_kernel, cudaFuncAttributeMaxDynamicSharedMemorySize, fused_smem);
    cudaFuncSetAttribute(pair_kernel, cudaFuncAttributeMaxDynamicSharedMemorySize,
                         (DIM * NT + DIM * 32) * 4 + DIM * 8);

    void *p_At, *p_Bt;
    cudaGetSymbolAddress(&p_At, g_At);
    cudaGetSymbolAddress(&p_Bt, g_Bt);

    const int nb_scan = (NNODES + 1 + 1023) / 1024;  // 79

    zero_kernel<<<(NNODES + 1 + 255) / 256, 256>>>();
    flag_kernel<<<(NG + 255) / 256, 256>>>(tf, gene);
    hist_kernel<<<(ne + 255) / 256, 256>>>(dst, ne);
    scan1_kernel<<<nb_scan, 1024>>>();
    scan2_kernel<<<1, 32>>>(nb_scan);
    scan3_kernel<<<nb_scan, 1024>>>();
    scatter_kernel<<<(ne + 255) / 256, 256>>>(src, dst, ne);
    agg1_csr_kernel<<<NNODES / 8, 256>>>(x);
    fused_gemm_kernel<<<NNODES / 64, 512, fused_smem>>>(W1, b1, W2);
    agg2_csr_kernel<<<NNODES / 8, 256>>>();
    half_mlp_kernel<<<NT, 128>>>(tf, NT, Wm1, b2, nullptr, (float*)p_At, NT);
    half_mlp_kernel<<<1000, 128>>>(gene, NG, Wm1 + 64 * DIM, b2, bm1, (float*)p_Bt, NG);
    pair_kernel<<<NG / 32, 256, (DIM * NT + DIM * 32) * 4 + DIM * 8>>>(Wm2, bm2, out);
}

// round 3
// speedup vs baseline: 1.9418x; 1.0428x over previous
#include <cuda_runtime.h>
#include <math.h>

#define NNODES 80000
#define DIM    128
#define DEMB   64
#define NT     128
#define NG     8000
#define NUMP   40000
#define NEMAX  2560000

typedef unsigned long long ull;

__device__ __forceinline__ ull ffma2(ull a, ull b, ull c) {
    ull d;
    asm("fma.rn.f32x2 %0, %1, %2, %3;" : "=l"(d) : "l"(a), "l"(b), "l"(c));
    return d;
}
__device__ __forceinline__ ull bcast2(float a) {
    ull d;
    asm("mov.b64 %0, {%1, %1};" : "=l"(d) : "f"(a));
    return d;
}
__device__ __forceinline__ float2 unpack2(ull v) {
    float2 f;
    asm("mov.b64 {%0, %1}, %2;" : "=f"(f.x), "=f"(f.y) : "l"(v));
    return f;
}

// ---------------- scratch (static device arrays; no allocation) ----------------
__device__ int g_rowptr[NNODES + 1];
__device__ int g_cursor[NNODES];
__device__ int g_flag[NNODES];
__device__ int g_bsum[128];
__device__ int g_esrc[NEMAX];                                // CSR: src per edge, grouped by dst
__device__ __align__(16) float g_xa[(size_t)NNODES * DIM];   // agg1 output (pre-scaled by 1/deg)
__device__ __align__(16) float g_p [(size_t)NNODES * DEMB];  // relu(xa@W1+b1)@W2
__device__ __align__(16) float g_pa[(size_t)NNODES * DEMB];  // agg2 output (flagged rows only)
__device__ __align__(16) float g_At[DIM * NT];               // A transposed [k][t]
__device__ __align__(16) float g_Bt[(size_t)DIM * NG];       // B transposed [k][g]

// ---------------- zero counters/flags ----------------
__global__ void zero_kernel() {
    int i = blockIdx.x * blockDim.x + threadIdx.x;
    if (i <= NNODES) g_rowptr[i] = 0;
    if (i <  NNODES) g_flag[i] = 0;
}

__global__ void flag_kernel(const int* __restrict__ tf, const int* __restrict__ gene) {
    int i = blockIdx.x * blockDim.x + threadIdx.x;
    if (i < NT) g_flag[NUMP + tf[i]]   = 1;
    if (i < NG) g_flag[NUMP + gene[i]] = 1;
}

// ---------------- CSR build: histogram -> scan -> scatter ----------------
__global__ void hist_kernel(const int* __restrict__ dst, int ne) {
    int e = blockIdx.x * blockDim.x + threadIdx.x;
    if (e < ne) atomicAdd(&g_rowptr[dst[e] + 1], 1);
}

// block-level inclusive scan over g_rowptr (1024 elems per block)
__global__ __launch_bounds__(1024) void scan1_kernel() {
    __shared__ int wsum[32];
    int gid = blockIdx.x * 1024 + threadIdx.x;
    int lane = threadIdx.x & 31, wid = threadIdx.x >> 5;
    int s = (gid <= NNODES) ? g_rowptr[gid] : 0;
#pragma unroll
    for (int o = 1; o < 32; o <<= 1) { int t = __shfl_up_sync(0xffffffffu, s, o); if (lane >= o) s += t; }
    if (lane == 31) wsum[wid] = s;
    __syncthreads();
    if (wid == 0) {
        int w = wsum[lane];
#pragma unroll
        for (int o = 1; o < 32; o <<= 1) { int t = __shfl_up_sync(0xffffffffu, w, o); if (lane >= o) w += t; }
        wsum[lane] = w;
    }
    __syncthreads();
    if (wid > 0) s += wsum[wid - 1];
    if (gid <= NNODES) g_rowptr[gid] = s;
    if (threadIdx.x == 1023) g_bsum[blockIdx.x] = s;
}

// scan the block sums (single warp, serial chunks with carry)
__global__ void scan2_kernel(int nb) {
    int lane = threadIdx.x;
    int carry = 0;
    for (int base = 0; base < nb; base += 32) {
        int v = (base + lane < nb) ? g_bsum[base + lane] : 0;
#pragma unroll
        for (int o = 1; o < 32; o <<= 1) { int t = __shfl_up_sync(0xffffffffu, v, o); if (lane >= o) v += t; }
        v += carry;
        if (base + lane < nb) g_bsum[base + lane] = v;
        carry = __shfl_sync(0xffffffffu, v, 31);
    }
}

// add block offsets AND seed g_cursor = rowptr (start offsets)
__global__ __launch_bounds__(1024) void scan3_kernel() {
    int gid = blockIdx.x * 1024 + threadIdx.x;
    if (gid > NNODES) return;
    int v = g_rowptr[gid];
    if (blockIdx.x > 0) v += g_bsum[blockIdx.x - 1];
    g_rowptr[gid] = v;
    if (gid < NNODES) g_cursor[gid] = v;
}

__global__ void scatter_kernel(const int* __restrict__ src, const int* __restrict__ dst, int ne) {
    int e = blockIdx.x * blockDim.x + threadIdx.x;
    if (e >= ne) return;
    int pos = atomicAdd(&g_cursor[dst[e]], 1);
    g_esrc[pos] = src[e];
}

// ---------------- agg1 via CSR: xa[d] = mean_{s in N(d)} x[s]  (warp per dst) ----------------
__global__ __launch_bounds__(256) void agg1_csr_kernel(const float* __restrict__ x) {
    int d = blockIdx.x * 8 + (threadIdx.x >> 5);
    if (d >= NNODES) return;
    int lane = threadIdx.x & 31;
    int beg = g_rowptr[d], end = g_rowptr[d + 1];
    float4 acc = make_float4(0.f, 0.f, 0.f, 0.f);
    int j = beg;
    for (; j + 1 < end; j += 2) {
        int s0 = g_esrc[j], s1 = g_esrc[j + 1];
        float4 v0 = reinterpret_cast<const float4*>(x + (size_t)s0 * DIM)[lane];
        float4 v1 = reinterpret_cast<const float4*>(x + (size_t)s1 * DIM)[lane];
        acc.x += v0.x + v1.x; acc.y += v0.y + v1.y;
        acc.z += v0.z + v1.z; acc.w += v0.w + v1.w;
    }
    if (j < end) {
        int s0 = g_esrc[j];
        float4 v0 = reinterpret_cast<const float4*>(x + (size_t)s0 * DIM)[lane];
        acc.x += v0.x; acc.y += v0.y; acc.z += v0.z; acc.w += v0.w;
    }
    float inv = 1.f / fmaxf((float)(end - beg), 1.f);
    acc.x *= inv; acc.y *= inv; acc.z *= inv; acc.w *= inv;
    reinterpret_cast<float4*>(g_xa + (size_t)d * DIM)[lane] = acc;
}

// ---------------- agg2 via CSR (flagged dsts only): pa[d] = mean p[s] ----------------
__global__ __launch_bounds__(256) void agg2_csr_kernel() {
    int d = blockIdx.x * 8 + (threadIdx.x >> 5);
    if (d >= NNODES) return;
    if (!g_flag[d]) return;
    int lane = threadIdx.x & 31;
    int beg = g_rowptr[d], end = g_rowptr[d + 1];
    float2 acc = make_float2(0.f, 0.f);
    int j = beg;
    for (; j + 1 < end; j += 2) {
        int s0 = g_esrc[j], s1 = g_esrc[j + 1];
        float2 v0 = reinterpret_cast<const float2*>(g_p + (size_t)s0 * DEMB)[lane];
        float2 v1 = reinterpret_cast<const float2*>(g_p + (size_t)s1 * DEMB)[lane];
        acc.x += v0.x + v1.x; acc.y += v0.y + v1.y;
    }
    if (j < end) {
        int s0 = g_esrc[j];
        float2 v0 = reinterpret_cast<const float2*>(g_p + (size_t)s0 * DEMB)[lane];
        acc.x += v0.x; acc.y += v0.y;
    }
    float inv = 1.f / fmaxf((float)(end - beg), 1.f);
    reinterpret_cast<float2*>(g_pa + (size_t)d * DEMB)[lane] = make_float2(acc.x * inv, acc.y * inv);
}

// ---------------- fused GEMM: p = relu(xa@W1 + b1) @ W2   (64 rows/block, 512 threads, FFMA2) ------
__global__ __launch_bounds__(512) void fused_gemm_kernel(
    const float* __restrict__ W1, const float* __restrict__ b1,
    const float* __restrict__ W2) {
    extern __shared__ float sm[];
    float* W1s = sm;                       // 128*128
    float* W2s = W1s + 128 * 128;          // 128*64
    float* Is  = W2s + 128 * 64;           // 64*128
    float* Hs  = Is  + 64 * 128;           // 64*128
    float* b1s = Hs  + 64 * 128;           // 128
    int tid = threadIdx.x;

    for (int i = tid; i < 128 * 128 / 4; i += 512)
        reinterpret_cast<float4*>(W1s)[i] = reinterpret_cast<const float4*>(W1)[i];
    for (int i = tid; i < 128 * 64 / 4; i += 512)
        reinterpret_cast<float4*>(W2s)[i] = reinterpret_cast<const float4*>(W2)[i];
    if (tid < 128) b1s[tid] = b1[tid];

    int row0 = blockIdx.x * 64;  // 1250 blocks * 64 = 80000 exact
    for (int i = tid; i < 64 * DIM / 4; i += 512)
        reinterpret_cast<float4*>(Is)[i] =
            reinterpret_cast<const float4*>(g_xa + (size_t)row0 * DIM)[i];
    __syncthreads();

    int tr = tid >> 5, tc = tid & 31;   // tr 0..15, tc 0..31

    // phase 1: H = relu(Is @ W1 + b1); thread -> 4 rows x 4 cols (2 f32x2 pairs)
    {
        ull acc[4][2];
#pragma unroll
        for (int i = 0; i < 4; i++) { acc[i][0] = 0ull; acc[i][1] = 0ull; }

        for (int d0 = 0; d0 < DIM; d0 += 4) {
            float ar[4][4];
#pragma unroll
            for (int i = 0; i < 4; i++) {
                float4 t = reinterpret_cast<const float4*>(Is + (tr * 4 + i) * DIM)[d0 >> 2];
                ar[i][0] = t.x; ar[i][1] = t.y; ar[i][2] = t.z; ar[i][3] = t.w;
            }
#pragma unroll
            for (int dd = 0; dd < 4; dd++) {
                ulonglong2 wv = *reinterpret_cast<const ulonglong2*>(W1s + (d0 + dd) * 128 + tc * 4);
#pragma unroll
                for (int i = 0; i < 4; i++) {
                    ull ap = bcast2(ar[i][dd]);
                    acc[i][0] = ffma2(ap, wv.x, acc[i][0]);
                    acc[i][1] = ffma2(ap, wv.y, acc[i][1]);
                }
            }
        }
        float4 bv = reinterpret_cast<const float4*>(b1s)[tc];
#pragma unroll
        for (int i = 0; i < 4; i++) {
            float2 lo = unpack2(acc[i][0]);
            float2 hi = unpack2(acc[i][1]);
            float4 o;
            o.x = fmaxf(lo.x + bv.x, 0.f);
            o.y = fmaxf(lo.y + bv.y, 0.f);
            o.z = fmaxf(hi.x + bv.z, 0.f);
            o.w = fmaxf(hi.y + bv.w, 0.f);
            reinterpret_cast<float4*>(Hs + (tr * 4 + i) * DIM)[tc] = o;
        }
    }
    __syncthreads();

    // phase 2: P = Hs @ W2; thread -> 4 rows x 2 cols (1 f32x2 pair)
    {
        ull acc[4];
#pragma unroll
        for (int i = 0; i < 4; i++) acc[i] = 0ull;

        for (int d0 = 0; d0 < DIM; d0 += 4) {
            float ar[4][4];
#pragma unroll
            for (int i = 0; i < 4; i++) {
                float4 t = reinterpret_cast<const float4*>(Hs + (tr * 4 + i) * DIM)[d0 >> 2];
                ar[i][0] = t.x; ar[i][1] = t.y; ar[i][2] = t.z; ar[i][3] = t.w;
            }
#pragma unroll
            for (int dd = 0; dd < 4; dd++) {
                ull wp = *reinterpret_cast<const ull*>(W2s + (d0 + dd) * 64 + tc * 2);
#pragma unroll
                for (int i = 0; i < 4; i++)
                    acc[i] = ffma2(bcast2(ar[i][dd]), wp, acc[i]);
            }
        }
#pragma unroll
        for (int i = 0; i < 4; i++) {
            int row = row0 + tr * 4 + i;
            float2 o = unpack2(acc[i]);
            reinterpret_cast<float2*>(g_p + (size_t)row * DEMB)[tc] = o;
        }
    }
}

// ---------------- half-MLP: OutT[k][r] = sum_d (pa[node_r][d] + b2[d]) * Whalf[d][k] (+bm1[k]) ------
__global__ __launch_bounds__(128) void half_mlp_kernel(
    const int* __restrict__ list, int nrows,
    const float* __restrict__ Whalf, const float* __restrict__ b2,
    const float* __restrict__ bm1, float* __restrict__ OutT, int ldo) {
    __shared__ __align__(8) float Wst[128 * 66];   // transposed [t][d], pad 66 (even) for ull loads
    __shared__ __align__(8) float es[DEMB];
    int tid = threadIdx.x;  // 128 (= t)

#pragma unroll 4
    for (int d = 0; d < DEMB; d++) Wst[tid * 66 + d] = Whalf[d * DIM + tid];
    float base = bm1 ? bm1[tid] : 0.f;

    for (int r = blockIdx.x; r < nrows; r += gridDim.x) {
        __syncthreads();
        if (tid < DEMB) {
            int node = NUMP + list[r];
            es[tid] = g_pa[(size_t)node * DEMB + tid] + b2[tid];
        }
        __syncthreads();
        ull acc = 0ull;
#pragma unroll 8
        for (int d = 0; d < DEMB; d += 2) {
            ull ep = *reinterpret_cast<const ull*>(es + d);
            ull wp = *reinterpret_cast<const ull*>(Wst + tid * 66 + d);
            acc = ffma2(ep, wp, acc);
        }
        float2 a2 = unpack2(acc);
        OutT[(size_t)tid * ldo + r] = base + a2.x + a2.y;
    }
}

// ---------------- pair kernel: out[t*NG+g] = softmax( relu(A[t]+B[g]) @ Wm2 + bm2 ) ----------------
__global__ __launch_bounds__(256) void pair_kernel(
    const float* __restrict__ Wm2, const float* __restrict__ bm2, float* __restrict__ out) {
    extern __shared__ float sm[];
    float* As = sm;                       // [k][t] 128*128
    float* Bs = sm + DIM * NT;            // [k][gl] 128*32
    float2* w2 = reinterpret_cast<float2*>(sm + DIM * NT + DIM * 32);
    int tid = threadIdx.x;  // 256

    for (int i = tid; i < DIM * NT / 4; i += 256)
        reinterpret_cast<float4*>(As)[i] = reinterpret_cast<const float4*>(g_At)[i];
    int g0 = blockIdx.x * 32;
    for (int i = tid; i < DIM * 32; i += 256) {
        int k = i >> 5, gl = i & 31;
        Bs[i] = g_Bt[(size_t)k * NG + g0 + gl];
    }
    if (tid < DIM) w2[tid] = reinterpret_cast<const float2*>(Wm2)[tid];
    __syncthreads();

    float bo0 = bm2[0], bo1 = bm2[1];
    int lane = tid & 31, warp = tid >> 5;
    ull accp[16];
#pragma unroll
    for (int i = 0; i < 16; i++) accp[i] = 0ull;

#pragma unroll 4
    for (int k = 0; k < DIM; k++) {
        float bv = Bs[k * 32 + lane];
        ull wp = *reinterpret_cast<const ull*>(&w2[k]);
#pragma unroll
        for (int i = 0; i < 16; i++) {
            float a = As[k * DIM + warp + 8 * i];
            float v = fmaxf(a + bv, 0.f);
            accp[i] = ffma2(bcast2(v), wp, accp[i]);
        }
    }

#pragma unroll
    for (int i = 0; i < 16; i++) {
        int t = warp + 8 * i;
        float2 a2 = unpack2(accp[i]);
        float o0 = a2.x + bo0, o1 = a2.y + bo1;
        float m  = fmaxf(o0, o1);
        float e0 = __expf(o0 - m), e1 = __expf(o1 - m);
        float inv = 1.f / (e0 + e1);
        reinterpret_cast<float2*>(out)[(size_t)t * NG + g0 + lane] = make_float2(e0 * inv, e1 * inv);
    }
}

// ---------------- launch ----------------
extern "C" void kernel_launch(void* const* d_in, const int* in_sizes, int n_in,
                              void* d_out, int out_size) {
    const float* x   = (const float*)d_in[0];
    const float* W1  = (const float*)d_in[1];
    const float* b1  = (const float*)d_in[2];
    const float* W2  = (const float*)d_in[3];
    const float* b2  = (const float*)d_in[4];
    const float* Wm1 = (const float*)d_in[5];
    const float* bm1 = (const float*)d_in[6];
    const float* Wm2 = (const float*)d_in[7];
    const float* bm2 = (const float*)d_in[8];
    const int* edges = (const int*)d_in[9];
    const int* tf    = (const int*)d_in[11];
    const int* gene  = (const int*)d_in[12];
    int ne = in_sizes[9] / 2;
    const int* src = edges;
    const int* dst = edges + ne;
    float* out = (float*)d_out;

    const int fused_smem = (128 * 128 + 128 * 64 + 64 * 128 + 64 * 128 + 128) * 4;
    cudaFuncSetAttribute(fused_gemm_kernel, cudaFuncAttributeMaxDynamicSharedMemorySize, fused_smem);
    cudaFuncSetAttribute(pair_kernel, cudaFuncAttributeMaxDynamicSharedMemorySize,
                         (DIM * NT + DIM * 32) * 4 + DIM * 8);

    void *p_At, *p_Bt;
    cudaGetSymbolAddress(&p_At, g_At);
    cudaGetSymbolAddress(&p_Bt, g_Bt);

    const int nb_scan = (NNODES + 1 + 1023) / 1024;  // 79

    zero_kernel<<<(NNODES + 1 + 255) / 256, 256>>>();
    flag_kernel<<<(NG + 255) / 256, 256>>>(tf, gene);
    hist_kernel<<<(ne + 255) / 256, 256>>>(dst, ne);
    scan1_kernel<<<nb_scan, 1024>>>();
    scan2_kernel<<<1, 32>>>(nb_scan);
    scan3_kernel<<<nb_scan, 1024>>>();
    scatter_kernel<<<(ne + 255) / 256, 256>>>(src, dst, ne);
    agg1_csr_kernel<<<NNODES / 8, 256>>>(x);
    fused_gemm_kernel<<<NNODES / 64, 512, fused_smem>>>(W1, b1, W2);
    agg2_csr_kernel<<<NNODES / 8, 256>>>();
    half_mlp_kernel<<<NT, 128>>>(tf, NT, Wm1, b2, nullptr, (float*)p_At, NT);
    half_mlp_kernel<<<1000, 128>>>(gene, NG, Wm1 + 64 * DIM, b2, bm1, (float*)p_Bt, NG);
    pair_kernel<<<NG / 32, 256, (DIM * NT + DIM * 32) * 4 + DIM * 8>>>(Wm2, bm2, out);
}